// round 3
// baseline (speedup 1.0000x reference)
#include <cuda_runtime.h>
#include <cstdint>

// B=8, S=512, V=32000, D=4096, r=16, E=4
#define TOKS   4096
#define SLEN   512
#define SPLITL 32
#define DDIM   4096
#define VDIM   32000
#define SCALE  2.0f   // lora_alpha / r

#define TTOK   64     // tokens per tile
#define TD     256    // d per tile (128 threads * 2)

typedef unsigned long long u64;

__device__ __forceinline__ u64 pk2(float lo, float hi) {
    u64 r; asm("mov.b64 %0, {%1, %2};" : "=l"(r) : "f"(lo), "f"(hi)); return r;
}
__device__ __forceinline__ void upk2(u64 v, float& lo, float& hi) {
    asm("mov.b64 {%0, %1}, %2;" : "=f"(lo), "=f"(hi) : "l"(v));
}
__device__ __forceinline__ u64 add2(u64 a, u64 b) {
    u64 r; asm("add.rn.f32x2 %0, %1, %2;" : "=l"(r) : "l"(a), "l"(b)); return r;
}
__device__ __forceinline__ void fma2(u64& acc, u64 a, u64 b) {
    asm("fma.rn.f32x2 %0, %1, %2, %0;" : "+l"(acc) : "l"(a), "l"(b));
}

// ---------------------------------------------------------------------------
// One fused kernel. Grid (64 token-tiles, 16 d-tiles) = 1024 CTAs of 128 thr.
// Each thread owns a d-pair: 32 packed {B[d],B[d+1]} f32x2 register pairs
// (B1+B2), reused over 64 tokens. Per-token c vectors (router * SCALE * A col)
// computed in-block: threads 0-63 handle A1, 64-127 handle A2 for the same
// token, halving the prologue chain. c stored duplicated in smem, broadcast
// via LDS.128. Base gather software-pipelined depth 4; streaming stores.
// 4 CTAs/SM (launch_bounds 128,4) -> 16 warps/SM; 1024 CTAs >> 592 residency
// so the CTA scheduler load-balances.
// ---------------------------------------------------------------------------
__global__ __launch_bounds__(128, 4) void fused_k(
    const int*   __restrict__ xw,
    const float* __restrict__ emb,
    const float* __restrict__ A1, const float* __restrict__ B1,
    const float* __restrict__ A2, const float* __restrict__ B2,
    const float* __restrict__ Wi, const float* __restrict__ bi,
    const float* __restrict__ Wt, const float* __restrict__ bt,
    float* __restrict__ out)
{
    __shared__ __align__(16) ulonglong2 sc2[16][TTOK];  // [k-pair][token] dup pairs
    __shared__ int      stok[TTOK];
    __shared__ unsigned sdet[4];

    const int tid   = threadIdx.x;
    const int ttile = blockIdx.x;
    const int d0    = blockIdx.y * TD + tid * 2;

    // --- dtype detect: odd 32-bit words of first 256 x-words all zero <=> int64 ---
    {
        int hiw = xw[2 * tid + 1];                     // words 1..255, in-bounds both ways
        unsigned ball = __ballot_sync(0xffffffffu, hiw != 0);
        if ((tid & 31) == 0) sdet[tid >> 5] = ball;
    }

    // --- pack B rows d0, d0+1 into 32 f32x2 register pairs ---
    u64 Bp[32];
    {
        const float4* r0 = (const float4*)(B1 + (size_t)(d0 + 0) * 16);
        const float4* r1 = (const float4*)(B1 + (size_t)(d0 + 1) * 16);
#pragma unroll
        for (int q = 0; q < 4; q++) {
            float4 a = r0[q], b = r1[q];
            Bp[q*4+0] = pk2(a.x, b.x);
            Bp[q*4+1] = pk2(a.y, b.y);
            Bp[q*4+2] = pk2(a.z, b.z);
            Bp[q*4+3] = pk2(a.w, b.w);
        }
        const float4* s0 = (const float4*)(B2 + (size_t)(d0 + 0) * 16);
        const float4* s1 = (const float4*)(B2 + (size_t)(d0 + 1) * 16);
#pragma unroll
        for (int q = 0; q < 4; q++) {
            float4 a = s0[q], b = s1[q];
            Bp[16+q*4+0] = pk2(a.x, b.x);
            Bp[16+q*4+1] = pk2(a.y, b.y);
            Bp[16+q*4+2] = pk2(a.z, b.z);
            Bp[16+q*4+3] = pk2(a.w, b.w);
        }
    }
    __syncthreads();

    // --- c phase: half 0 -> A1 (kk 0..7), half 1 -> A2 (kk 8..15), same token ---
    {
        const bool is64 = ((sdet[0] | sdet[1] | sdet[2] | sdet[3]) == 0);
        const int  half = tid >> 6;
        const int  t    = tid & 63;
        const int  i    = ttile * TTOK + t;
        const int  tok  = is64 ? xw[2 * i] : xw[i];
        if (half == 0) stok[t] = tok;
        const int s = i & (SLEN - 1);
        const float* W = (s < SPLITL) ? Wi : Wt;
        const float* b = (s < SPLITL) ? bi : bt;
        float l0 = W[tok] + b[0];
        float l1 = W[VDIM + tok] + b[1];
        float w0 = 1.0f / (1.0f + expf(l1 - l0));
        float sA = half ? (SCALE - w0 * SCALE) : (w0 * SCALE);
        const float* Am = half ? A2 : A1;
        float c[16];
#pragma unroll
        for (int r = 0; r < 16; r++) c[r] = sA * Am[(size_t)r * VDIM + tok];
#pragma unroll
        for (int kk = 0; kk < 8; kk++) {
            ulonglong2 v;
            v.x = pk2(c[2 * kk],     c[2 * kk]);
            v.y = pk2(c[2 * kk + 1], c[2 * kk + 1]);
            sc2[half * 8 + kk][t] = v;
        }
    }
    __syncthreads();

    // --- main loop over 64 tokens, prefetch depth 4 ---
    const size_t ob = (size_t)(ttile * TTOK) * DDIM + d0;
    float2 pf[4];
#pragma unroll
    for (int j = 0; j < 4; j++)
        pf[j] = __ldg((const float2*)(emb + (size_t)stok[j] * DDIM + d0));

#pragma unroll 1
    for (int t0 = 0; t0 < TTOK; t0 += 4) {
        float2 cur[4];
#pragma unroll
        for (int j = 0; j < 4; j++) cur[j] = pf[j];
        if (t0 + 4 < TTOK) {
#pragma unroll
            for (int j = 0; j < 4; j++)
                pf[j] = __ldg((const float2*)(emb + (size_t)stok[t0 + 4 + j] * DDIM + d0));
        }
#pragma unroll
        for (int j = 0; j < 4; j++) {
            const int t = t0 + j;
            u64 a0 = 0ull, a1 = 0ull, a2 = 0ull, a3 = 0ull;
#pragma unroll
            for (int kk = 0; kk < 16; kk += 2) {
                ulonglong2 ca = sc2[kk][t];          // LDS.128 broadcast
                ulonglong2 cb = sc2[kk + 1][t];
                fma2(a0, Bp[2 * kk],     ca.x);
                fma2(a1, Bp[2 * kk + 1], ca.y);
                fma2(a2, Bp[2 * kk + 2], cb.x);
                fma2(a3, Bp[2 * kk + 3], cb.y);
            }
            u64 r = add2(add2(a0, a1), add2(a2, a3));
            r = add2(r, pk2(cur[j].x, cur[j].y));
            float2 o;
            upk2(r, o.x, o.y);
            __stcs((float2*)(out + ob + (size_t)t * DDIM), o);
        }
    }
}

// ---------------------------------------------------------------------------
extern "C" void kernel_launch(void* const* d_in, const int* in_sizes, int n_in,
                              void* d_out, int out_size) {
    const int*   x   = (const int*)d_in[0];
    const float* emb = (const float*)d_in[1];
    const float* A1  = (const float*)d_in[2];
    const float* B1  = (const float*)d_in[3];
    const float* A2  = (const float*)d_in[4];
    const float* B2  = (const float*)d_in[5];
    const float* Wi  = (const float*)d_in[6];
    const float* bi  = (const float*)d_in[7];
    const float* Wt  = (const float*)d_in[8];
    const float* bt  = (const float*)d_in[9];
    float* out = (float*)d_out;

    fused_k<<<dim3(TOKS / TTOK, DDIM / TD), 128>>>(
        x, emb, A1, B1, A2, B2, Wi, bi, Wt, bt, out);
}

// round 4
// speedup vs baseline: 1.1720x; 1.1720x over previous
#include <cuda_runtime.h>
#include <cstdint>

// B=8, S=512, V=32000, D=4096, r=16, E=4
#define TOKS   4096
#define SLEN   512
#define SPLITL 32
#define DDIM   4096
#define VDIM   32000
#define SCALE  2.0f   // lora_alpha / r

#define TTOK   64     // tokens per tile
#define TD     256    // d per tile (128 threads * d-span 2)
#define CPAD   36     // padded c-row stride in floats (bank-conflict-free, 16B aligned)

typedef unsigned long long u64;

__device__ __forceinline__ void upk2(u64 v, float& lo, float& hi) {
    asm("mov.b64 {%0, %1}, %2;" : "=f"(lo), "=f"(hi) : "l"(v));
}
__device__ __forceinline__ u64 add2(u64 a, u64 b) {
    u64 r; asm("add.rn.f32x2 %0, %1, %2;" : "=l"(r) : "l"(a), "l"(b)); return r;
}
__device__ __forceinline__ void fma2(u64& acc, u64 a, u64 b) {
    asm("fma.rn.f32x2 %0, %1, %2, %0;" : "+l"(acc) : "l"(a), "l"(b));
}

// ---------------------------------------------------------------------------
// One fused kernel. Grid (64 token-tiles, 16 d-tiles) = 1024 CTAs, 128 thr.
// Thread owns d-pair (d0,d0+1). k is packed PAIRWISE: acc lanes hold partial
// sums over even/odd k; one horizontal add per output at the end. So:
//   - B pairs {B[d,2j],B[d,2j+1]} are contiguous memory -> raw u64 row loads
//   - c rows in smem are plain floats -> 8 broadcast LDS.128 per token
//     feeding 32 fma2 (1:4), no duplication
// c-phase: threads 0-63 do A1 (k 0..15), 64-127 do A2 (k 16..31), same token.
// 4 CTAs/SM (16 warps) to cover LDS/LDG latency; prefetch depth 4 on gather.
// int64/int32 detection: odd words of first 256 x-words all zero <=> int64.
// ---------------------------------------------------------------------------
__global__ __launch_bounds__(128, 4) void fused_k(
    const int*   __restrict__ xw,
    const float* __restrict__ emb,
    const float* __restrict__ A1, const float* __restrict__ B1,
    const float* __restrict__ A2, const float* __restrict__ B2,
    const float* __restrict__ Wi, const float* __restrict__ bi,
    const float* __restrict__ Wt, const float* __restrict__ bt,
    float* __restrict__ out)
{
    __shared__ __align__(16) float scf[TTOK * CPAD];   // c[t][k], padded rows
    __shared__ int      stok[TTOK];
    __shared__ unsigned sdet[4];

    const int tid   = threadIdx.x;
    const int ttile = blockIdx.x;
    const int d0    = blockIdx.y * TD + tid * 2;

    // --- dtype detect ---
    {
        int hiw = xw[2 * tid + 1];                    // words 1..255, in-bounds both ways
        unsigned ball = __ballot_sync(0xffffffffu, hiw != 0);
        if ((tid & 31) == 0) sdet[tid >> 5] = ball;
    }

    // --- B rows straight into u64 pairs: Bp{A,B}[j] = {B[d,2j],B[d,2j+1]} ---
    u64 BpA[16], BpB[16];
    {
        const ulonglong2* r;
        r = (const ulonglong2*)(B1 + (size_t)(d0 + 0) * 16);
#pragma unroll
        for (int q = 0; q < 4; q++) { ulonglong2 v = r[q]; BpA[2*q] = v.x; BpA[2*q+1] = v.y; }
        r = (const ulonglong2*)(B2 + (size_t)(d0 + 0) * 16);
#pragma unroll
        for (int q = 0; q < 4; q++) { ulonglong2 v = r[q]; BpA[8+2*q] = v.x; BpA[8+2*q+1] = v.y; }
        r = (const ulonglong2*)(B1 + (size_t)(d0 + 1) * 16);
#pragma unroll
        for (int q = 0; q < 4; q++) { ulonglong2 v = r[q]; BpB[2*q] = v.x; BpB[2*q+1] = v.y; }
        r = (const ulonglong2*)(B2 + (size_t)(d0 + 1) * 16);
#pragma unroll
        for (int q = 0; q < 4; q++) { ulonglong2 v = r[q]; BpB[8+2*q] = v.x; BpB[8+2*q+1] = v.y; }
    }
    __syncthreads();

    // --- c phase: half 0 -> A1 (k 0..15), half 1 -> A2 (k 16..31) ---
    {
        const bool is64 = ((sdet[0] | sdet[1] | sdet[2] | sdet[3]) == 0);
        const int  half = tid >> 6;
        const int  t    = tid & 63;
        const int  i    = ttile * TTOK + t;
        const int  tok  = is64 ? xw[2 * i] : xw[i];
        if (half == 0) stok[t] = tok;
        const int s = i & (SLEN - 1);
        const float* W = (s < SPLITL) ? Wi : Wt;
        const float* b = (s < SPLITL) ? bi : bt;
        float l0 = W[tok] + b[0];
        float l1 = W[VDIM + tok] + b[1];
        float w0 = 1.0f / (1.0f + expf(l1 - l0));
        float sA = half ? (SCALE - w0 * SCALE) : (w0 * SCALE);
        const float* Am = half ? A2 : A1;
        float c[16];
#pragma unroll
        for (int r = 0; r < 16; r++) c[r] = sA * Am[(size_t)r * VDIM + tok];
        float4* dst = (float4*)(scf + t * CPAD + half * 16);
#pragma unroll
        for (int q = 0; q < 4; q++)
            dst[q] = make_float4(c[4*q], c[4*q+1], c[4*q+2], c[4*q+3]);
    }
    __syncthreads();

    // --- main loop over 64 tokens, prefetch depth 4 on the base gather ---
    const size_t ob = (size_t)(ttile * TTOK) * DDIM + d0;
    float2 pf[4];
#pragma unroll
    for (int j = 0; j < 4; j++)
        pf[j] = __ldg((const float2*)(emb + (size_t)stok[j] * DDIM + d0));

#pragma unroll 1
    for (int t0 = 0; t0 < TTOK; t0 += 4) {
        float2 cur[4];
#pragma unroll
        for (int j = 0; j < 4; j++) cur[j] = pf[j];
        if (t0 + 4 < TTOK) {
#pragma unroll
            for (int j = 0; j < 4; j++)
                pf[j] = __ldg((const float2*)(emb + (size_t)stok[t0 + 4 + j] * DDIM + d0));
        }
#pragma unroll
        for (int j = 0; j < 4; j++) {
            const int t = t0 + j;
            const ulonglong2* cr = (const ulonglong2*)(scf + t * CPAD);
            u64 aA0 = 0ull, aA1 = 0ull, aB0 = 0ull, aB1 = 0ull;
#pragma unroll
            for (int jj = 0; jj < 8; jj++) {
                ulonglong2 cc = cr[jj];               // LDS.128 broadcast, plain c pairs
                fma2(aA0, BpA[2*jj],     cc.x);
                fma2(aA1, BpA[2*jj + 1], cc.y);
                fma2(aB0, BpB[2*jj],     cc.x);
                fma2(aB1, BpB[2*jj + 1], cc.y);
            }
            u64 sA = add2(aA0, aA1);
            u64 sB = add2(aB0, aB1);
            float alo, ahi, blo, bhi;
            upk2(sA, alo, ahi);
            upk2(sB, blo, bhi);
            float2 o;
            o.x = cur[j].x + (alo + ahi);
            o.y = cur[j].y + (blo + bhi);
            __stcs((float2*)(out + ob + (size_t)t * DDIM), o);
        }
    }
}

// ---------------------------------------------------------------------------
extern "C" void kernel_launch(void* const* d_in, const int* in_sizes, int n_in,
                              void* d_out, int out_size) {
    const int*   x   = (const int*)d_in[0];
    const float* emb = (const float*)d_in[1];
    const float* A1  = (const float*)d_in[2];
    const float* B1  = (const float*)d_in[3];
    const float* A2  = (const float*)d_in[4];
    const float* B2  = (const float*)d_in[5];
    const float* Wi  = (const float*)d_in[6];
    const float* bi  = (const float*)d_in[7];
    const float* Wt  = (const float*)d_in[8];
    const float* bt  = (const float*)d_in[9];
    float* out = (float*)d_out;

    fused_k<<<dim3(TOKS / TTOK, DDIM / TD), 128>>>(
        x, emb, A1, B1, A2, B2, Wi, bi, Wt, bt, out);
}